// round 4
// baseline (speedup 1.0000x reference)
#include <cuda_runtime.h>

// 2-level 2D Haar DWT, fully fused, 4x4 input tile per thread.
// Cache policy: input = default (L2-cached, persists across graph replays,
// 100.7MB fits in 126MB L2); output = streaming stores (evict-first) so the
// written data does not evict the resident input.
//
// x: [96, 512, 512] fp32.
// out layout (tuple order):
//   a2,h2,v2,d2 : [96,128,128]  (L2ELEMS each)
//   h1,v1,d1    : [96,256,256]  (4*L2ELEMS each)

#define L2ELEMS (96u * 128u * 128u)   // 1,572,864

// 2x2 Haar butterfly: inputs (tl,tr,bl,br) -> (aa, h, v, d)
#define BFLY(tl, tr, bl, br, aa, hh, vv, dd)          \
    {                                                  \
        float _sT = (tl) + (tr), _sB = (bl) + (br);    \
        float _dT = (tl) - (tr), _dB = (bl) - (br);    \
        aa = 0.5f * (_sT + _sB);                       \
        hh = 0.5f * (_sT - _sB);                       \
        vv = 0.5f * (_dT + _dB);                       \
        dd = 0.5f * (_dT - _dB);                       \
    }

__global__ void __launch_bounds__(256) haar2_kernel(const float* __restrict__ x,
                                                    float* __restrict__ out)
{
    unsigned tid = blockIdx.x * blockDim.x + threadIdx.x;   // 0 .. 96*128*128-1
    unsigned w  = tid & 127u;           // block col (of 4-wide blocks)
    unsigned h  = (tid >> 7) & 127u;    // block row
    unsigned bc = tid >> 14;            // batch*channel, 0..95

    const float4* xp = (const float4*)(x + ((size_t)bc * 512u + 4u * h) * 512u + 4u * w);
    float4 r0 = xp[0];
    float4 r1 = xp[128];
    float4 r2 = xp[256];
    float4 r3 = xp[384];

    // ---- level-1: four 2x2 butterflies ----
    float aa00, aa01, aa10, aa11;
    float2 h1r0, h1r1, v1r0, v1r1, d1r0, d1r1;

    BFLY(r0.x, r0.y, r1.x, r1.y, aa00, h1r0.x, v1r0.x, d1r0.x);
    BFLY(r0.z, r0.w, r1.z, r1.w, aa01, h1r0.y, v1r0.y, d1r0.y);
    BFLY(r2.x, r2.y, r3.x, r3.y, aa10, h1r1.x, v1r1.x, d1r1.x);
    BFLY(r2.z, r2.w, r3.z, r3.w, aa11, h1r1.y, v1r1.y, d1r1.y);

    // ---- level-2 butterfly on aa's ----
    float a2v, h2v, v2v, d2v;
    BFLY(aa00, aa01, aa10, aa11, a2v, h2v, v2v, d2v);

    // ---- streaming stores ----
    float* h1o = out + (size_t)4 * L2ELEMS;
    float* v1o = out + (size_t)8 * L2ELEMS;
    float* d1o = out + (size_t)12 * L2ELEMS;

    // level-1: [96,256,256], rows 2h/2h+1, cols 2w..2w+1 -> float2
    size_t base1 = (size_t)bc * 65536u + (size_t)(2u * h) * 256u + 2u * w;
    __stcs((float2*)(h1o + base1),        h1r0);
    __stcs((float2*)(h1o + base1 + 256),  h1r1);
    __stcs((float2*)(v1o + base1),        v1r0);
    __stcs((float2*)(v1o + base1 + 256),  v1r1);
    __stcs((float2*)(d1o + base1),        d1r0);
    __stcs((float2*)(d1o + base1 + 256),  d1r1);

    // level-2: [96,128,128]
    size_t base2 = (size_t)bc * 16384u + (size_t)h * 128u + w;
    __stcs(out + base2,                        a2v);
    __stcs(out + (size_t)L2ELEMS     + base2,  h2v);
    __stcs(out + (size_t)2 * L2ELEMS + base2,  v2v);
    __stcs(out + (size_t)3 * L2ELEMS + base2,  d2v);
}

extern "C" void kernel_launch(void* const* d_in, const int* in_sizes, int n_in,
                              void* d_out, int out_size)
{
    const float* x = (const float*)d_in[0];
    float* out = (float*)d_out;
    // one thread per 4x4 input block
    unsigned total = 96u * 128u * 128u;
    haar2_kernel<<<total / 256u, 256u>>>(x, out);
}

// round 5
// speedup vs baseline: 1.0073x; 1.0073x over previous
#include <cuda_runtime.h>

// 2-level 2D Haar DWT, fully fused, 4x4 tile per thread,
// grid-strided software pipeline: loads for tile i+1 are issued before
// compute+stores of tile i, keeping DRAM requests continuously in flight.
//
// x: [96, 512, 512] fp32.
// out layout (tuple order):
//   a2,h2,v2,d2 : [96,128,128]  (L2ELEMS each)
//   h1,v1,d1    : [96,256,256]  (4*L2ELEMS each)

#define L2ELEMS (96u * 128u * 128u)   // 1,572,864 tiles == 1,572,864 L2 elems
#define NBLOCKS 1024u
#define NTHREADS 256u
#define ITERS 6                        // 1,572,864 / (1024*256) == 6 exactly

// 2x2 Haar butterfly: inputs (tl,tr,bl,br) -> (aa, h, v, d)
#define BFLY(tl, tr, bl, br, aa, hh, vv, dd)          \
    {                                                  \
        float _sT = (tl) + (tr), _sB = (bl) + (br);    \
        float _dT = (tl) - (tr), _dB = (bl) - (br);    \
        aa = 0.5f * (_sT + _sB);                       \
        hh = 0.5f * (_sT - _sB);                       \
        vv = 0.5f * (_dT + _dB);                       \
        dd = 0.5f * (_dT - _dB);                       \
    }

struct Tile { float4 r0, r1, r2, r3; };

__device__ __forceinline__ Tile load_tile(const float* __restrict__ x, unsigned t)
{
    unsigned w  = t & 127u;
    unsigned h  = (t >> 7) & 127u;
    unsigned bc = t >> 14;
    const float4* xp = (const float4*)(x + ((size_t)bc * 512u + 4u * h) * 512u + 4u * w);
    Tile T;
    T.r0 = xp[0];
    T.r1 = xp[128];
    T.r2 = xp[256];
    T.r3 = xp[384];
    return T;
}

__device__ __forceinline__ void compute_store(float* __restrict__ out, unsigned t, const Tile& T)
{
    unsigned w  = t & 127u;
    unsigned h  = (t >> 7) & 127u;
    unsigned bc = t >> 14;

    float aa00, aa01, aa10, aa11;
    float2 h1r0, h1r1, v1r0, v1r1, d1r0, d1r1;

    BFLY(T.r0.x, T.r0.y, T.r1.x, T.r1.y, aa00, h1r0.x, v1r0.x, d1r0.x);
    BFLY(T.r0.z, T.r0.w, T.r1.z, T.r1.w, aa01, h1r0.y, v1r0.y, d1r0.y);
    BFLY(T.r2.x, T.r2.y, T.r3.x, T.r3.y, aa10, h1r1.x, v1r1.x, d1r1.x);
    BFLY(T.r2.z, T.r2.w, T.r3.z, T.r3.w, aa11, h1r1.y, v1r1.y, d1r1.y);

    float a2v, h2v, v2v, d2v;
    BFLY(aa00, aa01, aa10, aa11, a2v, h2v, v2v, d2v);

    float* h1o = out + (size_t)4 * L2ELEMS;
    float* v1o = out + (size_t)8 * L2ELEMS;
    float* d1o = out + (size_t)12 * L2ELEMS;

    // level-1: [96,256,256], rows 2h/2h+1, cols 2w..2w+1
    size_t base1 = (size_t)bc * 65536u + (size_t)(2u * h) * 256u + 2u * w;
    *(float2*)(h1o + base1)        = h1r0;
    *(float2*)(h1o + base1 + 256)  = h1r1;
    *(float2*)(v1o + base1)        = v1r0;
    *(float2*)(v1o + base1 + 256)  = v1r1;
    *(float2*)(d1o + base1)        = d1r0;
    *(float2*)(d1o + base1 + 256)  = d1r1;

    // level-2: [96,128,128]
    size_t base2 = (size_t)bc * 16384u + (size_t)h * 128u + w;
    out[base2]                         = a2v;
    out[(size_t)L2ELEMS     + base2]   = h2v;
    out[(size_t)2 * L2ELEMS + base2]   = v2v;
    out[(size_t)3 * L2ELEMS + base2]   = d2v;
}

__global__ void __launch_bounds__(NTHREADS) haar2_kernel(const float* __restrict__ x,
                                                         float* __restrict__ out)
{
    const unsigned stride = NBLOCKS * NTHREADS;                  // 262144
    unsigned t = blockIdx.x * NTHREADS + threadIdx.x;

    Tile cur = load_tile(x, t);
    #pragma unroll
    for (int i = 0; i < ITERS - 1; ++i) {
        Tile nxt = load_tile(x, t + stride);   // prefetch next tile
        compute_store(out, t, cur);            // overlap with in-flight loads
        cur = nxt;
        t += stride;
    }
    compute_store(out, t, cur);
}

extern "C" void kernel_launch(void* const* d_in, const int* in_sizes, int n_in,
                              void* d_out, int out_size)
{
    const float* x = (const float*)d_in[0];
    float* out = (float*)d_out;
    haar2_kernel<<<NBLOCKS, NTHREADS>>>(x, out);
}